// round 1
// baseline (speedup 1.0000x reference)
#include <cuda_runtime.h>
#include <math.h>

// Problem constants (fixed by setup_inputs)
#define NXMIT 128
#define NELEM 128
#define NSAMP 2048
#define NX    128
#define NZ    1024

#define PI_F 3.14159265358979f
#define MIN_WIDTH 0.001f

__global__ __launch_bounds__(256, 4)
void das_kernel(const float* __restrict__ idata,
                const float* __restrict__ qdata,
                const float* __restrict__ grid,
                const float* __restrict__ rx_ori,
                const float* __restrict__ ele_pos,
                const float* __restrict__ tstart,
                const float* __restrict__ c_p,
                const float* __restrict__ fs_p,
                const float* __restrict__ fdemod_p,
                const float* __restrict__ fnum_p,
                float* __restrict__ out)
{
    __shared__ float sex[NELEM], sey[NELEM], sez[NELEM];
    const int t = threadIdx.x;
    if (t < NELEM) {
        sex[t] = ele_pos[t * 3 + 0];
        sey[t] = ele_pos[t * 3 + 1];
        sez[t] = ele_pos[t * 3 + 2];
    }
    __syncthreads();

    const int tid = blockIdx.x * blockDim.x + t;
    const int x = tid >> 10;        // tid / NZ
    const int z = tid & (NZ - 1);   // tid % NZ

    const float c      = *c_p;
    const float fs     = *fs_p;
    const float fdemod = *fdemod_p;
    const float fnum   = *fnum_p;

    const int dl = x * NXMIT / NX;
    const float ts = tstart[dl];

    const float* gp = grid + ((size_t)x * NZ + z) * 3;
    const float gx = gp[0], gy = gp[1], gz = gp[2];
    const float* rp = rx_ori + x * 3;
    const float dx0 = gx - rp[0], dy0 = gy - rp[1], dz0 = gz - rp[2];
    const float txdel = sqrtf(dx0 * dx0 + dy0 * dy0 + dz0 * dz0);

    // ---- Pass 1: count masked elements (M) — pure ALU, no memory ----
    int M = 0;
    #pragma unroll 8
    for (int e = 0; e < NELEM; e++) {
        const float vx = gx - sex[e];
        const float vz = gz - sez[e];
        // matches reference: |v_z / v_x| >= fnum  (IEEE: /0 -> inf -> true)
        const bool mask = (fabsf(vz / vx) >= fnum) || (fabsf(vx) <= MIN_WIDTH);
        M += mask ? 1 : 0;
    }
    const int   Msafe = (M > 1) ? M : 1;
    const float dAng  = 2.0f * PI_F / (float)Msafe;
    float cd, sd;
    sincosf(dAng, &sd, &cd);
    // running (cos, sin) of 2*pi*rank/Msafe, starting at rank = 0
    float ch = 1.0f, sh = 0.0f;

    const float inv_c     = 1.0f / c;
    const float inv_fs    = 1.0f / fs;
    const float two_pi_fd = 2.0f * PI_F * fdemod;
    const float zterm     = gz * 2.0f * inv_c;   // g_z * 2 / c

    const float* il = idata + (size_t)dl * NELEM * NSAMP;
    const float* ql = qdata + (size_t)dl * NELEM * NSAMP;

    float si = 0.0f, sq = 0.0f;

    // ---- Pass 2: full DAS over masked aperture ----
    #pragma unroll 2
    for (int e = 0; e < NELEM; e++) {
        const float vx = gx - sex[e];
        const float vy = gy - sey[e];
        const float vz = gz - sez[e];
        const bool mask = (fabsf(vz / vx) >= fnum) || (fabsf(vx) <= MIN_WIDTH);
        if (!mask) continue;   // apod == 0 exactly -> contributes nothing

        const float rxdel  = sqrtf(vx * vx + vy * vy + vz * vz);
        const float delays = ((txdel + rxdel) * inv_c - ts) * fs;

        const float s0 = floorf(delays);
        const float w  = delays - s0;
        const int   i0 = (int)s0;
        const int   i1 = i0 + 1;

        const float* ir = il + (size_t)e * NSAMP;
        const float* qr = ql + (size_t)e * NSAMP;

        float i0v = 0.0f, i1v = 0.0f, q0v = 0.0f, q1v = 0.0f;
        if (i0 >= 0 && i0 < NSAMP) { i0v = __ldg(ir + i0); q0v = __ldg(qr + i0); }
        if (i1 >= 0 && i1 < NSAMP) { i1v = __ldg(ir + i1); q1v = __ldg(qr + i1); }

        float ifoc = i0v * (1.0f - w) + i1v * w;
        float qfoc = q0v * (1.0f - w) + q1v * w;

        // phase rotation (fdemod == 0 => theta == 0 => identity, matches where())
        const float tshift = delays * inv_fs - zterm;
        const float theta  = two_pi_fd * tshift;
        float st, ct;
        sincosf(theta, &st, &ct);
        const float irot = ifoc * ct - qfoc * st;
        const float qrot = qfoc * ct + ifoc * st;

        // Hamming apodization via rotation recurrence
        const float ham  = 0.54f - 0.46f * ch;
        const float apod = (M > 1) ? ham : 1.0f;

        si = fmaf(irot, apod, si);
        sq = fmaf(qrot, apod, sq);

        // advance rank: rotate (ch, sh) by dAng
        const float nch = ch * cd - sh * sd;
        const float nsh = sh * cd + ch * sd;
        ch = nch; sh = nsh;
    }

    out[(size_t)x * NZ + z]                  = si;
    out[(size_t)NX * NZ + (size_t)x * NZ + z] = sq;
}

extern "C" void kernel_launch(void* const* d_in, const int* in_sizes, int n_in,
                              void* d_out, int out_size)
{
    const float* idata   = (const float*)d_in[0];
    const float* qdata   = (const float*)d_in[1];
    const float* grid    = (const float*)d_in[2];
    const float* rx_ori  = (const float*)d_in[3];
    const float* ele_pos = (const float*)d_in[4];
    const float* tstart  = (const float*)d_in[5];
    const float* c_p     = (const float*)d_in[6];
    const float* fs_p    = (const float*)d_in[7];
    const float* fdemod_p= (const float*)d_in[8];
    const float* fnum_p  = (const float*)d_in[9];
    float* out = (float*)d_out;

    const int total = NX * NZ;            // one thread per output pixel
    const int threads = 256;
    const int blocks = total / threads;   // 512
    das_kernel<<<blocks, threads>>>(idata, qdata, grid, rx_ori, ele_pos, tstart,
                                    c_p, fs_p, fdemod_p, fnum_p, out);
}

// round 3
// speedup vs baseline: 1.7588x; 1.7588x over previous
#include <cuda_runtime.h>
#include <math.h>

#define NXMIT 128
#define NELEM 128
#define NSAMP 2048
#define NX    128
#define NZ    1024

#define PI_F 3.14159265358979f
#define MIN_WIDTH 0.001f

__global__ __launch_bounds__(128, 8)
void das_kernel(const float* __restrict__ idata,
                const float* __restrict__ qdata,
                const float* __restrict__ grid,
                const float* __restrict__ rx_ori,
                const float* __restrict__ ele_pos,
                const float* __restrict__ tstart,
                const float* __restrict__ c_p,
                const float* __restrict__ fs_p,
                const float* __restrict__ fdemod_p,
                const float* __restrict__ fnum_p,
                float* __restrict__ out)
{
    __shared__ float sex[NELEM], sey[NELEM], sez[NELEM];
    const int t = threadIdx.x;
    if (t < NELEM) {
        sex[t] = ele_pos[t * 3 + 0];
        sey[t] = ele_pos[t * 3 + 1];
        sez[t] = ele_pos[t * 3 + 2];
    }
    __syncthreads();

    const int tid = blockIdx.x * blockDim.x + t;
    const int x = tid >> 10;        // tid / NZ
    const int z = tid & (NZ - 1);   // tid % NZ

    const float c      = *c_p;
    const float fs     = *fs_p;
    const float fdemod = *fdemod_p;
    const float fnum   = *fnum_p;

    const int dl = x * NXMIT / NX;
    const float ts = tstart[dl];

    const float* gp = grid + ((size_t)x * NZ + z) * 3;
    const float gx = gp[0], gy = gp[1], gz = gp[2];
    const float* rp = rx_ori + x * 3;
    const float dx0 = gx - rp[0], dy0 = gy - rp[1], dz0 = gz - rp[2];
    const float txdel = sqrtf(dx0 * dx0 + dy0 * dy0 + dz0 * dz0);

    // ---- Aperture interval [lo, hi]: closed-form guess + exact-predicate fixup ----
    // Both mask conditions are |vx| <= threshold -> masked set is contiguous in e.
    // Exact predicate matches the reference bit-for-bit (incl. the division).
    #define PRED(E) ({                                            \
        const float _vx = gx - sex[(E)];                          \
        const float _vz = gz - sez[(E)];                          \
        (fabsf(_vz / _vx) >= fnum) || (fabsf(_vx) <= MIN_WIDTH); })

    const float pitch  = sex[1] - sex[0];
    const float half_w = fmaxf(gz / fnum, MIN_WIDTH);
    int lo = (int)ceilf ((gx - half_w - sex[0]) / pitch);
    int hi = (int)floorf((gx + half_w - sex[0]) / pitch);
    lo = max(0, min(lo, NELEM));
    hi = max(-1, min(hi, NELEM - 1));
    while (lo > 0         &&  PRED(lo - 1)) lo--;
    while (lo < NELEM     && !PRED(lo))     lo++;
    while (hi < NELEM - 1 &&  PRED(hi + 1)) hi++;
    while (hi >= 0        && !PRED(hi))     hi--;
    #undef PRED

    const int M = hi - lo + 1;

    float si = 0.0f, sq = 0.0f;

    if (M > 0) {
        const int   Msafe = (M > 1) ? M : 1;
        const float dAng  = 2.0f * PI_F / (float)Msafe;
        float cd, sd;
        sincosf(dAng, &sd, &cd);         // once per thread: accurate version
        float ch = 1.0f, sh = 0.0f;      // (cos, sin) of 2*pi*rank/Msafe, rank=0

        const float inv_c     = 1.0f / c;
        const float inv_fs    = 1.0f / fs;
        const float two_pi_fd = 2.0f * PI_F * fdemod;
        const float zterm     = gz * 2.0f * inv_c;
        const bool  useHam    = (M > 1);

        const float* il = idata + (size_t)dl * NELEM * NSAMP;
        const float* ql = qdata + (size_t)dl * NELEM * NSAMP;

        #pragma unroll 4
        for (int e = lo; e <= hi; e++) {
            const float vx = gx - sex[e];
            const float vy = gy - sey[e];
            const float vz = gz - sez[e];

            const float rxdel  = sqrtf(fmaf(vx, vx, fmaf(vy, vy, vz * vz)));
            const float delays = ((txdel + rxdel) * inv_c - ts) * fs;

            const float s0 = floorf(delays);
            const float w  = delays - s0;
            const int   i0 = (int)s0;
            const int   i1 = i0 + 1;

            const float* ir = il + (size_t)e * NSAMP;
            const float* qr = ql + (size_t)e * NSAMP;

            float i0v = 0.0f, i1v = 0.0f, q0v = 0.0f, q1v = 0.0f;
            if ((unsigned)i0 < NSAMP) { i0v = __ldg(ir + i0); q0v = __ldg(qr + i0); }
            if ((unsigned)i1 < NSAMP) { i1v = __ldg(ir + i1); q1v = __ldg(qr + i1); }

            const float ifoc = fmaf(w, i1v - i0v, i0v);
            const float qfoc = fmaf(w, q1v - q0v, q0v);

            // phase rotation: theta <= ~100 rad, __sincosf HW-reduction error ~2e-5
            const float theta = two_pi_fd * fmaf(delays, inv_fs, -zterm);
            float st, ct;
            __sincosf(theta, &st, &ct);
            const float irot = ifoc * ct - qfoc * st;
            const float qrot = fmaf(qfoc, ct, ifoc * st);

            const float ham  = fmaf(-0.46f, ch, 0.54f);
            const float apod = useHam ? ham : 1.0f;

            si = fmaf(irot, apod, si);
            sq = fmaf(qrot, apod, sq);

            // advance rank: rotate (ch, sh) by dAng
            const float nch = fmaf(ch, cd, -sh * sd);
            const float nsh = fmaf(sh, cd,  ch * sd);
            ch = nch; sh = nsh;
        }
    }

    out[(size_t)x * NZ + z]                   = si;
    out[(size_t)NX * NZ + (size_t)x * NZ + z] = sq;
}

extern "C" void kernel_launch(void* const* d_in, const int* in_sizes, int n_in,
                              void* d_out, int out_size)
{
    const float* idata   = (const float*)d_in[0];
    const float* qdata   = (const float*)d_in[1];
    const float* grid    = (const float*)d_in[2];
    const float* rx_ori  = (const float*)d_in[3];
    const float* ele_pos = (const float*)d_in[4];
    const float* tstart  = (const float*)d_in[5];
    const float* c_p     = (const float*)d_in[6];
    const float* fs_p    = (const float*)d_in[7];
    const float* fdemod_p= (const float*)d_in[8];
    const float* fnum_p  = (const float*)d_in[9];
    float* out = (float*)d_out;

    const int total = NX * NZ;
    const int threads = 128;
    const int blocks = total / threads;   // 1024
    das_kernel<<<blocks, threads>>>(idata, qdata, grid, rx_ori, ele_pos, tstart,
                                    c_p, fs_p, fdemod_p, fnum_p, out);
}